// round 6
// baseline (speedup 1.0000x reference)
#include <cuda_runtime.h>
#include <math.h>

#define BB 4
#define NN 512
#define DIM 512
#define HEADS 8
#define DH 64
#define DEPTH 4
#define ROWS (BB*NN)          // 2048
#define ATT_SCALE 0.125f
#define LN_EPS 1e-5f

// ---------------- scratch (static device memory; no allocation) -------------
__device__ float g_x_r [ROWS*DIM];
__device__ float g_x_i [ROWS*DIM];
__device__ float g_xn_r[ROWS*DIM];
__device__ float g_xn_i[ROWS*DIM];
__device__ float g_w_r [ROWS*DIM];
__device__ float g_w_i [ROWS*DIM];
__device__ float g_at_r[ROWS*DIM];
__device__ float g_at_i[ROWS*DIM];
__device__ float g_d_r [BB*HEADS*NN*NN];
__device__ float g_d_i [BB*HEADS*NN*NN];

// ---------------- f32x2 / async helpers -------------------------------------
typedef unsigned long long u64t;

__device__ __forceinline__ u64t dup2(float s){
    u64t r; asm("mov.b64 %0, {%1, %1};" : "=l"(r) : "f"(s)); return r;
}
__device__ __forceinline__ void fma2(u64t &d, u64t a, u64t b){
    asm("fma.rn.f32x2 %0, %1, %2, %0;" : "+l"(d) : "l"(a), "l"(b));
}
__device__ __forceinline__ float2 up2(u64t v){
    float2 f; asm("mov.b64 {%0, %1}, %2;" : "=f"(f.x), "=f"(f.y) : "l"(v)); return f;
}
__device__ __forceinline__ void cpa4(unsigned dst, const float* src){
    asm volatile("cp.async.ca.shared.global [%0], [%1], 4;" :: "r"(dst), "l"(src));
}
__device__ __forceinline__ void cpa16(unsigned dst, const float* src){
    asm volatile("cp.async.cg.shared.global [%0], [%1], 16;" :: "r"(dst), "l"(src));
}
#define CP_COMMIT() asm volatile("cp.async.commit_group;")
#define CP_WAIT1()  asm volatile("cp.async.wait_group 1;")

__device__ __forceinline__ float warp_sum(float v){
    #pragma unroll
    for (int o=16;o;o>>=1) v += __shfl_xor_sync(0xffffffffu, v, o);
    return v;
}
__device__ __forceinline__ float warp_max(float v){
    #pragma unroll
    for (int o=16;o;o>>=1) v = fmaxf(v, __shfl_xor_sync(0xffffffffu, v, o));
    return v;
}

// ---------------- copy in / out ---------------------------------------------
__global__ void copy_in_kernel(const float* __restrict__ a, const float* __restrict__ b,
                               float* __restrict__ xr, float* __restrict__ xi, int n){
    int i = blockIdx.x*blockDim.x + threadIdx.x;
    if (i < n){ xr[i] = a[i]; xi[i] = b[i]; }
}
__global__ void copy_out_kernel(const float* __restrict__ xr, const float* __restrict__ xi,
                                float* __restrict__ out, int n){
    int i = blockIdx.x*blockDim.x + threadIdx.x;
    if (i < n){ out[i] = xr[i]; out[n+i] = xi[i]; }
}

// ---------------- complex LayerNorm (per row of 512) ------------------------
__global__ __launch_bounds__(128)
void cln_kernel(const float* __restrict__ xr, const float* __restrict__ xi,
                const float* __restrict__ gr, const float* __restrict__ br,
                const float* __restrict__ gi, const float* __restrict__ bi,
                float* __restrict__ outr, float* __restrict__ outi)
{
    const int row = blockIdx.x;
    const int t   = threadIdx.x;
    const float4 vr = reinterpret_cast<const float4*>(xr + (size_t)row*DIM)[t];
    const float4 vi = reinterpret_cast<const float4*>(xi + (size_t)row*DIM)[t];

    float sr  = vr.x+vr.y+vr.z+vr.w;
    float s2r = vr.x*vr.x+vr.y*vr.y+vr.z*vr.z+vr.w*vr.w;
    float si  = vi.x+vi.y+vi.z+vi.w;
    float s2i = vi.x*vi.x+vi.y*vi.y+vi.z*vi.z+vi.w*vi.w;

    sr = warp_sum(sr); s2r = warp_sum(s2r); si = warp_sum(si); s2i = warp_sum(s2i);

    __shared__ float red[4][4];
    const int wid = t >> 5, lane = t & 31;
    if (lane == 0){ red[wid][0]=sr; red[wid][1]=s2r; red[wid][2]=si; red[wid][3]=s2i; }
    __syncthreads();
    float tr=0,t2r=0,ti=0,t2i=0;
    #pragma unroll
    for (int w=0; w<4; w++){ tr+=red[w][0]; t2r+=red[w][1]; ti+=red[w][2]; t2i+=red[w][3]; }

    const float inv = 1.0f/DIM;
    const float mr = tr*inv,  vvr = t2r*inv - mr*mr;
    const float mi = ti*inv,  vvi = t2i*inv - mi*mi;
    const float rr = rsqrtf(vvr + LN_EPS);
    const float ri = rsqrtf(vvi + LN_EPS);

    const float4 g4r = reinterpret_cast<const float4*>(gr)[t];
    const float4 b4r = reinterpret_cast<const float4*>(br)[t];
    const float4 g4i = reinterpret_cast<const float4*>(gi)[t];
    const float4 b4i = reinterpret_cast<const float4*>(bi)[t];

    float4 orr, oii;
    orr.x = (vr.x-mr)*rr*g4r.x + b4r.x;  oii.x = (vi.x-mi)*ri*g4i.x + b4i.x;
    orr.y = (vr.y-mr)*rr*g4r.y + b4r.y;  oii.y = (vi.y-mi)*ri*g4i.y + b4i.y;
    orr.z = (vr.z-mr)*rr*g4r.z + b4r.z;  oii.z = (vi.z-mi)*ri*g4i.z + b4i.z;
    orr.w = (vr.w-mr)*rr*g4r.w + b4r.w;  oii.w = (vi.w-mi)*ri*g4i.w + b4i.w;
    reinterpret_cast<float4*>(outr + (size_t)row*DIM)[t] = orr;
    reinterpret_cast<float4*>(outi + (size_t)row*DIM)[t] = oii;
}

// ---------------- magnitude softmax: one warp per row, no barriers ----------
__global__ __launch_bounds__(256)
void csoftmax_kernel(float* __restrict__ zr, float* __restrict__ zi)
{
    const int wid = threadIdx.x >> 5, lane = threadIdx.x & 31;
    const size_t row = (size_t)blockIdx.x*8 + wid;
    float* pr = zr + row*NN;
    float* pi = zi + row*NN;

    float4 vr[4], vi[4];
    #pragma unroll
    for (int u=0;u<4;u++){
        vr[u] = reinterpret_cast<const float4*>(pr)[lane + 32*u];
        vi[u] = reinterpret_cast<const float4*>(pi)[lane + 32*u];
    }
    float m[16];
    #pragma unroll
    for (int u=0;u<4;u++){
        m[4*u+0] = sqrtf(vr[u].x*vr[u].x + vi[u].x*vi[u].x);
        m[4*u+1] = sqrtf(vr[u].y*vr[u].y + vi[u].y*vi[u].y);
        m[4*u+2] = sqrtf(vr[u].z*vr[u].z + vi[u].z*vi[u].z);
        m[4*u+3] = sqrtf(vr[u].w*vr[u].w + vi[u].w*vi[u].w);
    }
    float mx = m[0];
    #pragma unroll
    for (int e=1;e<16;e++) mx = fmaxf(mx, m[e]);
    mx = warp_max(mx);

    float ex[16]; float s = 0.f;
    #pragma unroll
    for (int e=0;e<16;e++){ ex[e] = __expf(m[e] - mx); s += ex[e]; }
    s = warp_sum(s);
    const float inv = 1.0f / s;

    #pragma unroll
    for (int u=0;u<4;u++){
        float sc;
        sc = (m[4*u+0] > 0.f) ? ex[4*u+0]*inv/m[4*u+0] : 0.f;
        if (m[4*u+0] > 0.f){ vr[u].x *= sc; vi[u].x *= sc; } else { vr[u].x = ex[4*u+0]*inv; vi[u].x = 0.f; }
        sc = (m[4*u+1] > 0.f) ? ex[4*u+1]*inv/m[4*u+1] : 0.f;
        if (m[4*u+1] > 0.f){ vr[u].y *= sc; vi[u].y *= sc; } else { vr[u].y = ex[4*u+1]*inv; vi[u].y = 0.f; }
        sc = (m[4*u+2] > 0.f) ? ex[4*u+2]*inv/m[4*u+2] : 0.f;
        if (m[4*u+2] > 0.f){ vr[u].z *= sc; vi[u].z *= sc; } else { vr[u].z = ex[4*u+2]*inv; vi[u].z = 0.f; }
        sc = (m[4*u+3] > 0.f) ? ex[4*u+3]*inv/m[4*u+3] : 0.f;
        if (m[4*u+3] > 0.f){ vr[u].w *= sc; vi[u].w *= sc; } else { vr[u].w = ex[4*u+3]*inv; vi[u].w = 0.f; }
        reinterpret_cast<float4*>(pr)[lane + 32*u] = vr[u];
        reinterpret_cast<float4*>(pi)[lane + 32*u] = vi[u];
    }
}

// ======================= f32x2 complex GEMM (cp.async, 3-stage) ==============
#define BM 128
#define BN 64
#define BK 16
#define APAD 132           // row stride floats (528B, 16B aligned)
#define BPAD 68            // 272B, 16B aligned
#define A_STAGE_F (BK*APAD)      // 2112 floats
#define B_STAGE_F (BK*BPAD)      // 1088 floats
#define A_STAGE_B (A_STAGE_F*4)  // 8448 bytes
#define B_STAGE_B (B_STAGE_F*4)  // 4352 bytes
#define SMEM_BYTES (3*(2*A_STAGE_B + 2*B_STAGE_B))   // 76800

// compute body shared by NT/NN (reads A pairs via plain C++ 16B loads so the
// compiler can pipeline LDS across kk; no volatile fences in the hot loop)
template<bool CONJB>
__device__ __forceinline__ void gemm_body(const float* __restrict__ Ast_r,
                                          const float* __restrict__ Ast_i,
                                          const float* __restrict__ Bst_r,
                                          const float* __restrict__ Bst_i,
                                          int ty, int tx,
                                          u64t cr[4][4], u64t ci[4][4])
{
    const float* ArBase = Ast_r + ty*8;
    const float* AiBase = Ast_i + ty*8;
    #pragma unroll
    for (int kk = 0; kk < BK; kk++){
        u64t ar[4], ai[4];
        const ulonglong2 arл0 = *reinterpret_cast<const ulonglong2*>(ArBase + kk*APAD);
        const ulonglong2 arл1 = *reinterpret_cast<const ulonglong2*>(ArBase + kk*APAD + 4);
        const ulonglong2 aiл0 = *reinterpret_cast<const ulonglong2*>(AiBase + kk*APAD);
        const ulonglong2 aiл1 = *reinterpret_cast<const ulonglong2*>(AiBase + kk*APAD + 4);
        ar[0] = arл0.x; ar[1] = arл0.y; ar[2] = arл1.x; ar[3] = arл1.y;
        ai[0] = aiл0.x; ai[1] = aiл0.y; ai[2] = aiл1.x; ai[3] = aiл1.y;

        const float4 b4r = *reinterpret_cast<const float4*>(Bst_r + kk*BPAD + (tx<<2));
        const float4 b4i = *reinterpret_cast<const float4*>(Bst_i + kk*BPAD + (tx<<2));
        const float brr[4] = {b4r.x,b4r.y,b4r.z,b4r.w};
        const float bii[4] = {b4i.x,b4i.y,b4i.z,b4i.w};
        #pragma unroll
        for (int j=0;j<4;j++){
            const u64t brd  = dup2(brr[j]);
            const u64t bid  = dup2(bii[j]);
            const u64t nbid = dup2(-bii[j]);
            #pragma unroll
            for (int ip=0;ip<4;ip++){
                if (CONJB){
                    fma2(cr[ip][j], ar[ip], brd);
                    fma2(cr[ip][j], ai[ip], bid);
                    fma2(ci[ip][j], ai[ip], brd);
                    fma2(ci[ip][j], ar[ip], nbid);
                } else {
                    fma2(cr[ip][j], ar[ip], brd);
                    fma2(cr[ip][j], ai[ip], nbid);
                    fma2(ci[ip][j], ar[ip], bid);
                    fma2(ci[ip][j], ai[ip], brd);
                }
            }
        }
    }
}

// ---- NT: C[m,n] = alpha * sum_k A[m,k] * (conj?) B[n,k] --------------------
template<int EPI, bool CONJB>
__global__ __launch_bounds__(256, 2)
void cgemm_nt_kernel(const float* __restrict__ Ar, const float* __restrict__ Ai, int lda,
                     const float* __restrict__ Br, const float* __restrict__ Bi, int ldb,
                     float* Cr, float* Ci, int ldc,
                     int K, float alpha,
                     size_t sAb, size_t sAh, size_t sBb, size_t sBh,
                     size_t sCb, size_t sCh,
                     const float* __restrict__ biasR, const float* __restrict__ biasI,
                     const float* __restrict__ Xr, const float* __restrict__ Xi,
                     const float* __restrict__ ssp, const float* __restrict__ lmp, int layer)
{
    extern __shared__ float dsm[];
    float* AsR = dsm;
    float* AsI = AsR + 3*A_STAGE_F;
    float* BsR = AsI + 3*A_STAGE_F;
    float* BsI = BsR + 3*B_STAGE_F;
    const unsigned aR = (unsigned)__cvta_generic_to_shared(AsR);
    const unsigned aI = (unsigned)__cvta_generic_to_shared(AsI);
    const unsigned bR = (unsigned)__cvta_generic_to_shared(BsR);
    const unsigned bI = (unsigned)__cvta_generic_to_shared(BsI);

    const int zb = blockIdx.z >> 3, zh = blockIdx.z & 7;
    const size_t Aoff = (size_t)zb*sAb + (size_t)zh*sAh;
    const size_t Boff = (size_t)zb*sBb + (size_t)zh*sBh;
    const size_t Coff = (size_t)zb*sCb + (size_t)zh*sCh;

    const int m0 = blockIdx.y * BM;
    const int n0 = blockIdx.x * BN;

    const int tid = threadIdx.x;
    const int tx = tid & 15, ty = tid >> 4;

    const int kL = tid & 15;
    const int rL = tid >> 4;

    const float* gAr = Ar + Aoff + (size_t)(m0+rL)*lda + kL;
    const float* gAi = Ai + Aoff + (size_t)(m0+rL)*lda + kL;
    const float* gBr = Br + Boff + (size_t)(n0+rL)*ldb + kL;
    const float* gBi = Bi + Boff + (size_t)(n0+rL)*ldb + kL;

    const unsigned dAr = aR + kL*(APAD*4) + rL*4;
    const unsigned dAi = aI + kL*(APAD*4) + rL*4;
    const unsigned dBr = bR + kL*(BPAD*4) + rL*4;
    const unsigned dBi = bI + kL*(BPAD*4) + rL*4;

#define LOAD_NT(st, k0) do{                                              \
    const unsigned oA = (st)*A_STAGE_B, oB = (st)*B_STAGE_B;             \
    _Pragma("unroll")                                                    \
    for (int s=0;s<8;s++){                                               \
        cpa4(dAr + oA + s*64, gAr + (k0) + (size_t)(16*s)*lda);          \
        cpa4(dAi + oA + s*64, gAi + (k0) + (size_t)(16*s)*lda);          \
    }                                                                    \
    _Pragma("unroll")                                                    \
    for (int s=0;s<4;s++){                                               \
        cpa4(dBr + oB + s*64, gBr + (k0) + (size_t)(16*s)*ldb);          \
        cpa4(dBi + oB + s*64, gBi + (k0) + (size_t)(16*s)*ldb);          \
    }                                                                    \
    CP_COMMIT(); }while(0)

    u64t cr[4][4] = {}, ci[4][4] = {};

    const int NIT = K / BK;
    LOAD_NT(0, 0);
    if (NIT > 1) LOAD_NT(1, BK); else CP_COMMIT();

    int st = 0;
    for (int it = 0; it < NIT; it++){
        CP_WAIT1();
        __syncthreads();
        if (it + 2 < NIT){
            int stn = st + 2; if (stn >= 3) stn -= 3;
            LOAD_NT(stn, (it+2)*BK);
        } else {
            CP_COMMIT();
        }

        gemm_body<CONJB>(AsR + st*A_STAGE_F, AsI + st*A_STAGE_F,
                         BsR + st*B_STAGE_F, BsI + st*B_STAGE_F, ty, tx, cr, ci);
        st++; if (st == 3) st = 0;
    }
#undef LOAD_NT

    float ss = 0.f, lm = 0.f;
    if (EPI == 2){
        ss = log1pf(expf(ssp[layer]));
        lm = log1pf(expf(lmp[layer]));
    }

    #pragma unroll
    for (int ip=0;ip<4;ip++){
        const int gm = m0 + ty*8 + ip*2;
        #pragma unroll
        for (int j=0;j<4;j++){
            const int gn = n0 + (tx<<2) + j;
            float2 vr = up2(cr[ip][j]);
            float2 vi = up2(ci[ip][j]);
            vr.x *= alpha; vr.y *= alpha; vi.x *= alpha; vi.y *= alpha;
            const size_t i0 = Coff + (size_t)gm*ldc + gn;
            const size_t i1 = i0 + ldc;
            if (EPI == 0){
                Cr[i0] = vr.x; Ci[i0] = vi.x;
                Cr[i1] = vr.y; Ci[i1] = vi.y;
            } else if (EPI == 1){
                Cr[i0] = vr.x + biasR[gn] + Cr[i0];
                Ci[i0] = vi.x + biasI[gn] + Ci[i0];
                Cr[i1] = vr.y + biasR[gn] + Cr[i1];
                Ci[i1] = vi.y + biasI[gn] + Ci[i1];
            } else {
                const float x0r = Xr[(size_t)gm*ldc + gn];
                const float x0i = Xi[(size_t)gm*ldc + gn];
                const float x1r = Xr[(size_t)(gm+1)*ldc + gn];
                const float x1i = Xi[(size_t)(gm+1)*ldc + gn];
                Cr[i0] = fmaxf(fmaf(ss, vr.x, x0r) - ss*lm, 0.f);
                Ci[i0] = fmaxf(fmaf(ss, vi.x, x0i), 0.f);
                Cr[i1] = fmaxf(fmaf(ss, vr.y, x1r) - ss*lm, 0.f);
                Ci[i1] = fmaxf(fmaf(ss, vi.y, x1i), 0.f);
            }
        }
    }
}

// ---- NN: C[m,n] = sum_k A[m,k] * B[k,n] ------------------------------------
__global__ __launch_bounds__(256, 2)
void cgemm_nn_kernel(const float* __restrict__ Ar, const float* __restrict__ Ai, int lda,
                     const float* __restrict__ Br, const float* __restrict__ Bi, int ldb,
                     float* __restrict__ Cr, float* __restrict__ Ci, int ldc,
                     int K,
                     size_t sAb, size_t sAh, size_t sBb, size_t sBh,
                     size_t sCb, size_t sCh)
{
    extern __shared__ float dsm[];
    float* AsR = dsm;
    float* AsI = AsR + 3*A_STAGE_F;
    float* BsR = AsI + 3*A_STAGE_F;
    float* BsI = BsR + 3*B_STAGE_F;
    const unsigned aR = (unsigned)__cvta_generic_to_shared(AsR);
    const unsigned aI = (unsigned)__cvta_generic_to_shared(AsI);
    const unsigned bR = (unsigned)__cvta_generic_to_shared(BsR);
    const unsigned bI = (unsigned)__cvta_generic_to_shared(BsI);

    const int zb = blockIdx.z >> 3, zh = blockIdx.z & 7;
    const size_t Aoff = (size_t)zb*sAb + (size_t)zh*sAh;
    const size_t Boff = (size_t)zb*sBb + (size_t)zh*sBh;
    const size_t Coff = (size_t)zb*sCb + (size_t)zh*sCh;

    const int m0 = blockIdx.y * BM;
    const int n0 = blockIdx.x * BN;

    const int tid = threadIdx.x;
    const int tx = tid & 15, ty = tid >> 4;

    const int kL = tid & 15;
    const int rL = tid >> 4;
    const int ncB = (tid & 15) << 2;   // 0..60
    const int kB  = tid >> 4;          // 0..15

    const float* gAr = Ar + Aoff + (size_t)(m0+rL)*lda + kL;
    const float* gAi = Ai + Aoff + (size_t)(m0+rL)*lda + kL;
    const float* gBr = Br + Boff + (size_t)kB*ldb + n0 + ncB;
    const float* gBi = Bi + Boff + (size_t)kB*ldb + n0 + ncB;

    const unsigned dAr = aR + kL*(APAD*4) + rL*4;
    const unsigned dAi = aI + kL*(APAD*4) + rL*4;
    const unsigned dBr = bR + kB*(BPAD*4) + ncB*4;
    const unsigned dBi = bI + kB*(BPAD*4) + ncB*4;

#define LOAD_NN(st, k0) do{                                              \
    const unsigned oA = (st)*A_STAGE_B, oB = (st)*B_STAGE_B;             \
    _Pragma("unroll")                                                    \
    for (int s=0;s<8;s++){                                               \
        cpa4(dAr + oA + s*64, gAr + (k0) + (size_t)(16*s)*lda);          \
        cpa4(dAi + oA + s*64, gAi + (k0) + (size_t)(16*s)*lda);          \
    }                                                                    \
    cpa16(dBr + oB, gBr + (size_t)(k0)*ldb);                             \
    cpa16(dBi + oB, gBi + (size_t)(k0)*ldb);                             \
    CP_COMMIT(); }while(0)

    u64t cr[4][4] = {}, ci[4][4] = {};

    const int NIT = K / BK;
    LOAD_NN(0, 0);
    if (NIT > 1) LOAD_NN(1, BK); else CP_COMMIT();

    int st = 0;
    for (int it = 0; it < NIT; it++){
        CP_WAIT1();
        __syncthreads();
        if (it + 2 < NIT){
            int stn = st + 2; if (stn >= 3) stn -= 3;
            LOAD_NN(stn, (it+2)*BK);
        } else {
            CP_COMMIT();
        }

        gemm_body<false>(AsR + st*A_STAGE_F, AsI + st*A_STAGE_F,
                         BsR + st*B_STAGE_F, BsI + st*B_STAGE_F, ty, tx, cr, ci);
        st++; if (st == 3) st = 0;
    }
#undef LOAD_NN

    #pragma unroll
    for (int ip=0;ip<4;ip++){
        const int gm = m0 + ty*8 + ip*2;
        #pragma unroll
        for (int j=0;j<4;j++){
            const int gn = n0 + (tx<<2) + j;
            const float2 vr = up2(cr[ip][j]);
            const float2 vi = up2(ci[ip][j]);
            const size_t i0 = Coff + (size_t)gm*ldc + gn;
            const size_t i1 = i0 + ldc;
            Cr[i0] = vr.x; Ci[i0] = vi.x;
            Cr[i1] = vr.y; Ci[i1] = vi.y;
        }
    }
}

// ---------------- launch ----------------------------------------------------
extern "C" void kernel_launch(void* const* d_in, const int* in_sizes, int n_in,
                              void* d_out, int out_size)
{
    const float* x_real   = (const float*)d_in[0];
    const float* x_imag   = (const float*)d_in[1];
    const float* ln1_g_r  = (const float*)d_in[2];
    const float* ln1_b_r  = (const float*)d_in[3];
    const float* ln1_g_i  = (const float*)d_in[4];
    const float* ln1_b_i  = (const float*)d_in[5];
    const float* ln2_g_r  = (const float*)d_in[6];
    const float* ln2_b_r  = (const float*)d_in[7];
    const float* ln2_g_i  = (const float*)d_in[8];
    const float* ln2_b_i  = (const float*)d_in[9];
    const float* qkv_w_r  = (const float*)d_in[10];
    const float* qkv_w_i  = (const float*)d_in[11];
    const float* out_w_r  = (const float*)d_in[12];
    const float* out_w_i  = (const float*)d_in[13];
    const float* out_b_r  = (const float*)d_in[14];
    const float* out_b_i  = (const float*)d_in[15];
    const float* ff_w_r   = (const float*)d_in[16];
    const float* ff_w_i   = (const float*)d_in[17];
    const float* step_sz  = (const float*)d_in[18];
    const float* lambd    = (const float*)d_in[19];

    float *xr,*xi,*xnr,*xni,*wr,*wi,*ar,*ai,*dr,*di;
    cudaGetSymbolAddress((void**)&xr,  g_x_r);
    cudaGetSymbolAddress((void**)&xi,  g_x_i);
    cudaGetSymbolAddress((void**)&xnr, g_xn_r);
    cudaGetSymbolAddress((void**)&xni, g_xn_i);
    cudaGetSymbolAddress((void**)&wr,  g_w_r);
    cudaGetSymbolAddress((void**)&wi,  g_w_i);
    cudaGetSymbolAddress((void**)&ar,  g_at_r);
    cudaGetSymbolAddress((void**)&ai,  g_at_i);
    cudaGetSymbolAddress((void**)&dr,  g_d_r);
    cudaGetSymbolAddress((void**)&di,  g_d_i);

    cudaFuncSetAttribute(cgemm_nt_kernel<0,false>, cudaFuncAttributeMaxDynamicSharedMemorySize, SMEM_BYTES);
    cudaFuncSetAttribute(cgemm_nt_kernel<0,true >, cudaFuncAttributeMaxDynamicSharedMemorySize, SMEM_BYTES);
    cudaFuncSetAttribute(cgemm_nt_kernel<1,false>, cudaFuncAttributeMaxDynamicSharedMemorySize, SMEM_BYTES);
    cudaFuncSetAttribute(cgemm_nt_kernel<2,false>, cudaFuncAttributeMaxDynamicSharedMemorySize, SMEM_BYTES);
    cudaFuncSetAttribute(cgemm_nn_kernel,          cudaFuncAttributeMaxDynamicSharedMemorySize, SMEM_BYTES);

    const int NE = ROWS*DIM;
    copy_in_kernel<<<(NE+255)/256, 256>>>(x_real, x_imag, xr, xi, NE);

    const size_t sRow = (size_t)NN*DIM;
    const size_t sNN  = (size_t)NN*NN;

    for (int l = 0; l < DEPTH; l++){
        const size_t wo = (size_t)l*DIM*DIM;
        const size_t po = (size_t)l*DIM;

        // LN1
        cln_kernel<<<ROWS,128>>>(xr,xi, ln1_g_r+po, ln1_b_r+po, ln1_g_i+po, ln1_b_i+po, xnr,xni);
        // QKV: w = xn @ Wqkv^T
        cgemm_nt_kernel<0,false><<<dim3(8,16,1),256,SMEM_BYTES>>>(
            xnr,xni,DIM, qkv_w_r+wo,qkv_w_i+wo,DIM, wr,wi,DIM, DIM, 1.0f,
            0,0,0,0,0,0, nullptr,nullptr, nullptr,nullptr, nullptr,nullptr, 0);
        // dots[b,h] = scale * w @ conj(w)^T  (K=64)
        cgemm_nt_kernel<0,true><<<dim3(8,4,32),256,SMEM_BYTES>>>(
            wr,wi,DIM, wr,wi,DIM, dr,di,NN, DH, ATT_SCALE,
            sRow,(size_t)DH, sRow,(size_t)DH, (size_t)8*sNN, sNN,
            nullptr,nullptr, nullptr,nullptr, nullptr,nullptr, 0);
        // magnitude softmax (warp per row)
        csoftmax_kernel<<<BB*HEADS*NN/8,256>>>(dr,di);
        // att = attn @ w
        cgemm_nn_kernel<<<dim3(1,4,32),256,SMEM_BYTES>>>(
            dr,di,NN, wr,wi,DIM, ar,ai,DIM, NN,
            (size_t)8*sNN, sNN, sRow,(size_t)DH, sRow,(size_t)DH);
        // x = att @ Wout^T + bout + x
        cgemm_nt_kernel<1,false><<<dim3(8,16,1),256,SMEM_BYTES>>>(
            ar,ai,DIM, out_w_r+wo,out_w_i+wo,DIM, xr,xi,DIM, DIM, 1.0f,
            0,0,0,0,0,0, out_b_r+po,out_b_i+po, nullptr,nullptr, nullptr,nullptr, 0);
        // LN2
        cln_kernel<<<ROWS,128>>>(xr,xi, ln2_g_r+po, ln2_b_r+po, ln2_g_i+po, ln2_b_i+po, xnr,xni);
        // x = crelu(xn + ss*(xn @ Wff^T) - ss*lm)
        cgemm_nt_kernel<2,false><<<dim3(8,16,1),256,SMEM_BYTES>>>(
            xnr,xni,DIM, ff_w_r+wo,ff_w_i+wo,DIM, xr,xi,DIM, DIM, 1.0f,
            0,0,0,0,0,0, nullptr,nullptr, xnr,xni, step_sz,lambd, l);
    }

    copy_out_kernel<<<(NE+255)/256, 256>>>(xr, xi, (float*)d_out, NE);
}

// round 8
// speedup vs baseline: 1.5627x; 1.5627x over previous
#include <cuda_runtime.h>
#include <cuda_bf16.h>
#include <math.h>
#include <stdint.h>

#define BB 4
#define NN 512
#define DIM 512
#define HEADS 8
#define DH 64
#define DEPTH 4
#define ROWS (BB*NN)
#define ATT_SCALE 0.125f
#define LN_EPS 1e-5f
#define PLN (ROWS*DIM)          // 1048576
#define PLA (32*NN*NN)          // 8388608
#define WPL (DEPTH*DIM*DIM)     // 1048576

// ---------------- scratch ----------------------------------------------------
__device__ float g_x_r [PLN];
__device__ float g_x_i [PLN];
__device__ float g_xn_r[PLN];
__device__ float g_xn_i[PLN];
__device__ float g_d_r [PLA];
__device__ float g_d_i [PLA];
// bf16 planes: 0=re_hi 1=re_lo 2=im_hi 3=im_lo
__device__ alignas(16) __nv_bfloat16 g_xnb [4*PLN];
__device__ alignas(16) __nv_bfloat16 g_wb  [4*PLN];
__device__ alignas(16) __nv_bfloat16 g_wTb [4*PLN];
__device__ alignas(16) __nv_bfloat16 g_atb [4*PLN];
__device__ alignas(16) __nv_bfloat16 g_attnb[(size_t)4*PLA];
__device__ alignas(16) __nv_bfloat16 g_qkvb[4*WPL];
__device__ alignas(16) __nv_bfloat16 g_outb[4*WPL];
__device__ alignas(16) __nv_bfloat16 g_ffb [4*WPL];

// ---------------- helpers -----------------------------------------------------
__device__ __forceinline__ float warp_sum(float v){
    #pragma unroll
    for (int o=16;o;o>>=1) v += __shfl_xor_sync(0xffffffffu, v, o);
    return v;
}
__device__ __forceinline__ float warp_max(float v){
    #pragma unroll
    for (int o=16;o;o>>=1) v = fmaxf(v, __shfl_xor_sync(0xffffffffu, v, o));
    return v;
}
__device__ __forceinline__ void cpa16(unsigned dst, const void* src){
    asm volatile("cp.async.cg.shared.global [%0], [%1], 16;" :: "r"(dst), "l"(src));
}
#define CP_COMMIT() asm volatile("cp.async.commit_group;")
#define CP_WAIT1()  asm volatile("cp.async.wait_group 1;")
#define CP_WAIT0()  asm volatile("cp.async.wait_group 0;")

__device__ __forceinline__ void ldsm4(unsigned &r0,unsigned &r1,unsigned &r2,unsigned &r3,unsigned a){
    asm volatile("ldmatrix.sync.aligned.m8n8.x4.shared.b16 {%0,%1,%2,%3}, [%4];"
        : "=r"(r0),"=r"(r1),"=r"(r2),"=r"(r3) : "r"(a));
}
__device__ __forceinline__ void mmabf(float* d, const unsigned* a, const unsigned* b){
    asm volatile("mma.sync.aligned.m16n8k16.row.col.f32.bf16.bf16.f32 "
        "{%0,%1,%2,%3}, {%4,%5,%6,%7}, {%8,%9}, {%0,%1,%2,%3};"
        : "+f"(d[0]),"+f"(d[1]),"+f"(d[2]),"+f"(d[3])
        : "r"(a[0]),"r"(a[1]),"r"(a[2]),"r"(a[3]), "r"(b[0]),"r"(b[1]));
}

__device__ __forceinline__ void store_split4(__nv_bfloat16* p, size_t pl, size_t o, float4 v){
    __nv_bfloat16 h0=__float2bfloat16_rn(v.x), h1=__float2bfloat16_rn(v.y);
    __nv_bfloat16 h2=__float2bfloat16_rn(v.z), h3=__float2bfloat16_rn(v.w);
    *(__nv_bfloat162*)(p+o)   = __halves2bfloat162(h0,h1);
    *(__nv_bfloat162*)(p+o+2) = __halves2bfloat162(h2,h3);
    *(__nv_bfloat162*)(p+pl+o)   = __halves2bfloat162(
        __float2bfloat16_rn(v.x-__bfloat162float(h0)), __float2bfloat16_rn(v.y-__bfloat162float(h1)));
    *(__nv_bfloat162*)(p+pl+o+2) = __halves2bfloat162(
        __float2bfloat16_rn(v.z-__bfloat162float(h2)), __float2bfloat16_rn(v.w-__bfloat162float(h3)));
}

// ---------------- small kernels -----------------------------------------------
__global__ void copy_in_kernel(const float* __restrict__ a, const float* __restrict__ b,
                               float* __restrict__ xr, float* __restrict__ xi, int n){
    int i = blockIdx.x*blockDim.x + threadIdx.x;
    if (i < n){ xr[i] = a[i]; xi[i] = b[i]; }
}
__global__ void copy_out_kernel(const float* __restrict__ xr, const float* __restrict__ xi,
                                float* __restrict__ out, int n){
    int i = blockIdx.x*blockDim.x + threadIdx.x;
    if (i < n){ out[i] = xr[i]; out[n+i] = xi[i]; }
}
__global__ void conv_split_kernel(const float* __restrict__ r, const float* __restrict__ im,
                                  __nv_bfloat16* __restrict__ dst, int n){
    int x = blockIdx.x*blockDim.x + threadIdx.x;
    if (x >= n) return;
    float v = r[x];
    __nv_bfloat16 h = __float2bfloat16_rn(v);
    dst[x] = h; dst[n + x] = __float2bfloat16_rn(v - __bfloat162float(h));
    v = im[x];
    h = __float2bfloat16_rn(v);
    dst[2*(size_t)n + x] = h; dst[3*(size_t)n + x] = __float2bfloat16_rn(v - __bfloat162float(h));
}

__global__ __launch_bounds__(128)
void cln_kernel(const float* __restrict__ xr, const float* __restrict__ xi,
                const float* __restrict__ gr, const float* __restrict__ br,
                const float* __restrict__ gi, const float* __restrict__ bi,
                float* __restrict__ outr, float* __restrict__ outi,
                __nv_bfloat16* __restrict__ outb)
{
    const int row = blockIdx.x;
    const int t   = threadIdx.x;
    const float4 vr = reinterpret_cast<const float4*>(xr + (size_t)row*DIM)[t];
    const float4 vi = reinterpret_cast<const float4*>(xi + (size_t)row*DIM)[t];

    float sr  = vr.x+vr.y+vr.z+vr.w;
    float s2r = vr.x*vr.x+vr.y*vr.y+vr.z*vr.z+vr.w*vr.w;
    float si  = vi.x+vi.y+vi.z+vi.w;
    float s2i = vi.x*vi.x+vi.y*vi.y+vi.z*vi.z+vi.w*vi.w;

    sr = warp_sum(sr); s2r = warp_sum(s2r); si = warp_sum(si); s2i = warp_sum(s2i);

    __shared__ float red[4][4];
    const int wid = t >> 5, lane = t & 31;
    if (lane == 0){ red[wid][0]=sr; red[wid][1]=s2r; red[wid][2]=si; red[wid][3]=s2i; }
    __syncthreads();
    float tr=0,t2r=0,ti=0,t2i=0;
    #pragma unroll
    for (int w=0; w<4; w++){ tr+=red[w][0]; t2r+=red[w][1]; ti+=red[w][2]; t2i+=red[w][3]; }

    const float inv = 1.0f/DIM;
    const float mr = tr*inv,  vvr = t2r*inv - mr*mr;
    const float mi = ti*inv,  vvi = t2i*inv - mi*mi;
    const float rr = rsqrtf(vvr + LN_EPS);
    const float ri = rsqrtf(vvi + LN_EPS);

    const float4 g4r = reinterpret_cast<const float4*>(gr)[t];
    const float4 b4r = reinterpret_cast<const float4*>(br)[t];
    const float4 g4i = reinterpret_cast<const float4*>(gi)[t];
    const float4 b4i = reinterpret_cast<const float4*>(bi)[t];

    float4 orr, oii;
    orr.x = (vr.x-mr)*rr*g4r.x + b4r.x;  oii.x = (vi.x-mi)*ri*g4i.x + b4i.x;
    orr.y = (vr.y-mr)*rr*g4r.y + b4r.y;  oii.y = (vi.y-mi)*ri*g4i.y + b4i.y;
    orr.z = (vr.z-mr)*rr*g4r.z + b4r.z;  oii.z = (vi.z-mi)*ri*g4i.z + b4i.z;
    orr.w = (vr.w-mr)*rr*g4r.w + b4r.w;  oii.w = (vi.w-mi)*ri*g4i.w + b4i.w;
    reinterpret_cast<float4*>(outr + (size_t)row*DIM)[t] = orr;
    reinterpret_cast<float4*>(outi + (size_t)row*DIM)[t] = oii;

    const size_t o = (size_t)row*DIM + 4*t;
    store_split4(outb,                 PLN, o, orr);
    store_split4(outb + (size_t)2*PLN, PLN, o, oii);
}

__global__ __launch_bounds__(256)
void csoftmax_kernel(const float* __restrict__ zr, const float* __restrict__ zi,
                     __nv_bfloat16* __restrict__ attn)
{
    const int wid = threadIdx.x >> 5, lane = threadIdx.x & 31;
    const size_t row = (size_t)blockIdx.x*8 + wid;
    const float* pr = zr + row*NN;
    const float* pi = zi + row*NN;

    float4 vr[4], vi[4];
    #pragma unroll
    for (int u=0;u<4;u++){
        vr[u] = reinterpret_cast<const float4*>(pr)[lane + 32*u];
        vi[u] = reinterpret_cast<const float4*>(pi)[lane + 32*u];
    }
    float m[16];
    #pragma unroll
    for (int u=0;u<4;u++){
        m[4*u+0] = sqrtf(vr[u].x*vr[u].x + vi[u].x*vi[u].x);
        m[4*u+1] = sqrtf(vr[u].y*vr[u].y + vi[u].y*vi[u].y);
        m[4*u+2] = sqrtf(vr[u].z*vr[u].z + vi[u].z*vi[u].z);
        m[4*u+3] = sqrtf(vr[u].w*vr[u].w + vi[u].w*vi[u].w);
    }
    float mx = m[0];
    #pragma unroll
    for (int e=1;e<16;e++) mx = fmaxf(mx, m[e]);
    mx = warp_max(mx);

    float ex[16]; float s = 0.f;
    #pragma unroll
    for (int e=0;e<16;e++){ ex[e] = __expf(m[e] - mx); s += ex[e]; }
    s = warp_sum(s);
    const float inv = 1.0f / s;

    #pragma unroll
    for (int u=0;u<4;u++){
        float4 ar, ai;
        #pragma unroll
        for (int q=0;q<4;q++){
            const float mm = m[4*u+q];
            const float p  = ex[4*u+q]*inv;
            float wr = (q==0? vr[u].x : q==1? vr[u].y : q==2? vr[u].z : vr[u].w);
            float wi = (q==0? vi[u].x : q==1? vi[u].y : q==2? vi[u].z : vi[u].w);
            float orv, oiv;
            if (mm > 0.f){ const float sc = p/mm; orv = wr*sc; oiv = wi*sc; }
            else         { orv = p; oiv = 0.f; }
            if (q==0){ ar.x=orv; ai.x=oiv; } else if (q==1){ ar.y=orv; ai.y=oiv; }
            else if (q==2){ ar.z=orv; ai.z=oiv; } else { ar.w=orv; ai.w=oiv; }
        }
        const size_t o = row*NN + 4*(lane + 32*u);
        store_split4(attn,                 PLA, o, ar);
        store_split4(attn + (size_t)2*PLA, PLA, o, ai);
    }
}

// ================= mma.sync bf16 complex GEMM ==================================
#define RS 48
#define APLANE (128*RS)                 // 6144 B
#define BPLANE (64*RS)                  // 3072 B
#define STAGE_B (4*APLANE + 4*BPLANE)   // 36864 B
#define DSMEM_BYTES (2*STAGE_B + 128)

__device__ __forceinline__ void load_stage(unsigned sb,
    const __nv_bfloat16* A, size_t ap, int lda,
    const __nv_bfloat16* B, size_t bp, int ldb, int k0, int tid)
{
    const int row = tid >> 1, half = tid & 1;
    #pragma unroll
    for (int p=0;p<4;p++)
        cpa16(sb + p*APLANE + row*RS + half*16, A + p*ap + (size_t)row*lda + k0 + half*8);
    if (tid < 128){
        #pragma unroll
        for (int p=0;p<4;p++)
            cpa16(sb + 4*APLANE + p*BPLANE + row*RS + half*16, B + p*bp + (size_t)row*ldb + k0 + half*8);
    }
    CP_COMMIT();
}

template<bool CONJ>
__device__ __forceinline__ void compute_stage(unsigned sb, int wm, int wn, int lane,
    float cre[2][4][4], float cim[2][4][4])
{
    const unsigned aoff = (unsigned)((lane & 15)*RS + (lane >> 4)*16);
    const int bg = lane >> 3;
    const unsigned boff = (unsigned)((((bg & 2) << 2) + (lane & 7))*RS + (bg & 1)*16);

    unsigned Arh[2][4], Arl[2][4], Aih[2][4], Ail[2][4];
    #pragma unroll
    for (int mf=0; mf<2; mf++){
        const unsigned ab = sb + (unsigned)(wm + mf*16)*RS + aoff;
        ldsm4(Arh[mf][0],Arh[mf][1],Arh[mf][2],Arh[mf][3], ab);
        ldsm4(Arl[mf][0],Arl[mf][1],Arl[mf][2],Arl[mf][3], ab + APLANE);
        ldsm4(Aih[mf][0],Aih[mf][1],Aih[mf][2],Aih[mf][3], ab + 2*APLANE);
        ldsm4(Ail[mf][0],Ail[mf][1],Ail[mf][2],Ail[mf][3], ab + 3*APLANE);
    }
    unsigned Bh[4][2], Bl[4][2];
    // ---- half 1: B = real planes
    #pragma unroll
    for (int np=0; np<2; np++){
        const unsigned bb = sb + 4*APLANE + (unsigned)(wn + np*16)*RS + boff;
        unsigned r0,r1,r2,r3;
        ldsm4(r0,r1,r2,r3, bb);
        Bh[2*np][0]=r0; Bh[2*np][1]=r1; Bh[2*np+1][0]=r2; Bh[2*np+1][1]=r3;
        ldsm4(r0,r1,r2,r3, bb + BPLANE);
        Bl[2*np][0]=r0; Bl[2*np][1]=r1; Bl[2*np+1][0]=r2; Bl[2*np+1][1]=r3;
    }
    #pragma unroll
    for (int mf=0; mf<2; mf++)
    #pragma unroll
    for (int nf=0; nf<4; nf++){
        mmabf(cre[mf][nf], Arh[mf], Bh[nf]);
        mmabf(cre[mf][nf], Arh[mf], Bl[nf]);
        mmabf(cre[mf][nf], Arl[mf], Bh[nf]);
        mmabf(cim[mf][nf], Aih[mf], Bh[nf]);
        mmabf(cim[mf][nf], Aih[mf], Bl[nf]);
        mmabf(cim[mf][nf], Ail[mf], Bh[nf]);
    }
    // ---- half 2: B = imag planes
    #pragma unroll
    for (int np=0; np<2; np++){
        const unsigned bb = sb + 4*APLANE + 2*BPLANE + (unsigned)(wn + np*16)*RS + boff;
        unsigned r0,r1,r2,r3;
        ldsm4(r0,r1,r2,r3, bb);
        Bh[2*np][0]=r0; Bh[2*np][1]=r1; Bh[2*np+1][0]=r2; Bh[2*np+1][1]=r3;
        ldsm4(r0,r1,r2,r3, bb + BPLANE);
        Bl[2*np][0]=r0; Bl[2*np][1]=r1; Bl[2*np+1][0]=r2; Bl[2*np+1][1]=r3;
    }
    if (CONJ){
        // Cre += Ai*Bi (positive)
        #pragma unroll
        for (int mf=0; mf<2; mf++)
        #pragma unroll
        for (int nf=0; nf<4; nf++){
            mmabf(cre[mf][nf], Aih[mf], Bh[nf]);
            mmabf(cre[mf][nf], Aih[mf], Bl[nf]);
            mmabf(cre[mf][nf], Ail[mf], Bh[nf]);
        }
        // negate B in place, then Cim += Ar*(-Bi)
        #pragma unroll
        for (int nf=0; nf<4; nf++){
            Bh[nf][0]^=0x80008000u; Bh[nf][1]^=0x80008000u;
            Bl[nf][0]^=0x80008000u; Bl[nf][1]^=0x80008000u;
        }
        #pragma unroll
        for (int mf=0; mf<2; mf++)
        #pragma unroll
        for (int nf=0; nf<4; nf++){
            mmabf(cim[mf][nf], Arh[mf], Bh[nf]);
            mmabf(cim[mf][nf], Arh[mf], Bl[nf]);
            mmabf(cim[mf][nf], Arl[mf], Bh[nf]);
        }
    } else {
        // Cim += Ar*Bi (positive)
        #pragma unroll
        for (int mf=0; mf<2; mf++)
        #pragma unroll
        for (int nf=0; nf<4; nf++){
            mmabf(cim[mf][nf], Arh[mf], Bh[nf]);
            mmabf(cim[mf][nf], Arh[mf], Bl[nf]);
            mmabf(cim[mf][nf], Arl[mf], Bh[nf]);
        }
        // negate B in place, then Cre += Ai*(-Bi)
        #pragma unroll
        for (int nf=0; nf<4; nf++){
            Bh[nf][0]^=0x80008000u; Bh[nf][1]^=0x80008000u;
            Bl[nf][0]^=0x80008000u; Bl[nf][1]^=0x80008000u;
        }
        #pragma unroll
        for (int mf=0; mf<2; mf++)
        #pragma unroll
        for (int nf=0; nf<4; nf++){
            mmabf(cre[mf][nf], Aih[mf], Bh[nf]);
            mmabf(cre[mf][nf], Aih[mf], Bl[nf]);
            mmabf(cre[mf][nf], Ail[mf], Bh[nf]);
        }
    }
}

// EPI: 0=W (w planes + wT planes), 1=DOTS (fp32*alpha), 2=AT (planes),
//      3=OUT (x += acc + bias), 4=FF (crelu)
template<int EPI, bool CONJ>
__global__ __launch_bounds__(256, 1)
void mma_gemm(const __nv_bfloat16* __restrict__ Ab, size_t ap, int lda, size_t aB, size_t aBH,
              const __nv_bfloat16* __restrict__ Bb, size_t bp, int ldb, size_t bB, size_t bBH,
              int K, float alpha,
              float* Cr, float* Ci, int ldc, size_t cB, size_t cBH,
              __nv_bfloat16* Ob, size_t op,
              __nv_bfloat16* OTb, size_t otp,
              const float* __restrict__ biasR, const float* __restrict__ biasI,
              const float* __restrict__ Xr, const float* __restrict__ Xi,
              const float* __restrict__ ssp, const float* __restrict__ lmp, int layer)
{
    extern __shared__ char dsmc[];
    const unsigned base = ((unsigned)__cvta_generic_to_shared(dsmc) + 127u) & ~127u;

    const int tid = threadIdx.x;
    const int lane = tid & 31, wid = tid >> 5;
    const int wm = (wid & 3)*32, wn = (wid >> 2)*32;
    const int zb = blockIdx.z >> 3, zh = blockIdx.z & 7;
    const int m0 = blockIdx.y * 128, n0 = blockIdx.x * 64;

    const __nv_bfloat16* At = Ab + (size_t)zb*aB + (size_t)zh*aBH + (size_t)m0*lda;
    const __nv_bfloat16* Bt = Bb + (size_t)zb*bB + (size_t)zh*bBH + (size_t)n0*ldb;
    const size_t Coff = (size_t)zb*cB + (size_t)zh*cBH;

    float cre[2][4][4] = {}, cim[2][4][4] = {};

    const int NIT = K >> 4;
    load_stage(base, At, ap, lda, Bt, bp, ldb, 0, tid);
    if (NIT > 1) load_stage(base + STAGE_B, At, ap, lda, Bt, bp, ldb, 16, tid);

    for (int it = 0; it < NIT; it++){
        if (it + 1 < NIT) CP_WAIT1(); else CP_WAIT0();
        __syncthreads();
        const unsigned sb = base + (unsigned)(it & 1)*STAGE_B;
        compute_stage<CONJ>(sb, wm, wn, lane, cre, cim);
        __syncthreads();
        if (it + 2 < NIT)
            load_stage(sb, At, ap, lda, Bt, bp, ldb, (it+2) << 4, tid);
    }

    float ss = 0.f, lm = 0.f;
    if (EPI == 4){ ss = log1pf(expf(ssp[layer])); lm = log1pf(expf(lmp[layer])); }

    #pragma unroll
    for (int mf=0; mf<2; mf++)
    #pragma unroll
    for (int nf=0; nf<4; nf++){
        const int row0 = m0 + wm + mf*16 + (lane >> 2);
        const int col  = n0 + wn + nf*8 + (lane & 3)*2;
        #pragma unroll
        for (int h=0; h<2; h++){
            const int r = row0 + h*8;
            float vr0 = cre[mf][nf][2*h]   * alpha;
            float vr1 = cre[mf][nf][2*h+1] * alpha;
            float vi0 = cim[mf][nf][2*h]   * alpha;
            float vi1 = cim[mf][nf][2*h+1] * alpha;
            const size_t a = Coff + (size_t)r*ldc + col;
            if (EPI == 1){
                Cr[a] = vr0; Cr[a+1] = vr1; Ci[a] = vi0; Ci[a+1] = vi1;
            } else if (EPI == 3){
                Cr[a]   = vr0 + biasR[col]   + Cr[a];
                Cr[a+1] = vr1 + biasR[col+1] + Cr[a+1];
                Ci[a]   = vi0 + biasI[col]   + Ci[a];
                Ci[a+1] = vi1 + biasI[col+1] + Ci[a+1];
            } else if (EPI == 4){
                Cr[a]   = fmaxf(fmaf(ss, vr0, Xr[a])   - ss*lm, 0.f);
                Cr[a+1] = fmaxf(fmaf(ss, vr1, Xr[a+1]) - ss*lm, 0.f);
                Ci[a]   = fmaxf(fmaf(ss, vi0, Xi[a]),   0.f);
                Ci[a+1] = fmaxf(fmaf(ss, vi1, Xi[a+1]), 0.f);
            } else {
                __nv_bfloat16 h0 = __float2bfloat16_rn(vr0), h1 = __float2bfloat16_rn(vr1);
                *(__nv_bfloat162*)(Ob + a) = __halves2bfloat162(h0, h1);
                *(__nv_bfloat162*)(Ob + op + a) = __halves2bfloat162(
                    __float2bfloat16_rn(vr0 - __bfloat162float(h0)),
                    __float2bfloat16_rn(vr1 - __bfloat162float(h1)));
                __nv_bfloat16 g0 = __float2bfloat16_rn(vi0), g1 = __float2bfloat16_rn(vi1);
                *(__nv_bfloat162*)(Ob + 2*op + a) = __halves2bfloat162(g0, g1);
                *(__nv_bfloat162*)(Ob + 3*op + a) = __halves2bfloat162(
                    __float2bfloat16_rn(vi0 - __bfloat162float(g0)),
                    __float2bfloat16_rn(vi1 - __bfloat162float(g1)));
                if (EPI == 0){
                    #pragma unroll
                    for (int q=0; q<2; q++){
                        const int cq = col + q;
                        const float wr = (q? vr1 : vr0), wi2 = (q? vi1 : vi0);
                        const size_t aT = ((size_t)((r >> 9)*8 + (cq >> 6))*64 + (cq & 63))*512 + (r & 511);
                        __nv_bfloat16 th = __float2bfloat16_rn(wr);
                        OTb[aT] = th; OTb[otp + aT] = __float2bfloat16_rn(wr - __bfloat162float(th));
                        th = __float2bfloat16_rn(wi2);
                        OTb[2*otp + aT] = th; OTb[3*otp + aT] = __float2bfloat16_rn(wi2 - __bfloat162float(th));
                    }
                }
            }
        }
    }
}

// ---------------- launch --------------------------------------------------------
extern "C" void kernel_launch(void* const* d_in, const int* in_sizes, int n_in,
                              void* d_out, int out_size)
{
    const float* x_real   = (const float*)d_in[0];
    const float* x_imag   = (const float*)d_in[1];
    const float* ln1_g_r  = (const float*)d_in[2];
    const float* ln1_b_r  = (const float*)d_in[3];
    const float* ln1_g_i  = (const float*)d_in[4];
    const float* ln1_b_i  = (const float*)d_in[5];
    const float* ln2_g_r  = (const float*)d_in[6];
    const float* ln2_b_r  = (const float*)d_in[7];
    const float* ln2_g_i  = (const float*)d_in[8];
    const float* ln2_b_i  = (const float*)d_in[9];
    const float* qkv_w_r  = (const float*)d_in[10];
    const float* qkv_w_i  = (const float*)d_in[11];
    const float* out_w_r  = (const float*)d_in[12];
    const float* out_w_i  = (const float*)d_in[13];
    const float* out_b_r  = (const float*)d_in[14];
    const float* out_b_i  = (const float*)d_in[15];
    const float* ff_w_r   = (const float*)d_in[16];
    const float* ff_w_i   = (const float*)d_in[17];
    const float* step_sz  = (const float*)d_in[18];
    const float* lambd    = (const float*)d_in[19];

    float *xr,*xi,*xnr,*xni,*dr,*di;
    __nv_bfloat16 *xnb,*wb,*wTb,*atb,*attnb,*qkvb,*outb,*ffb;
    cudaGetSymbolAddress((void**)&xr,   g_x_r);
    cudaGetSymbolAddress((void**)&xi,   g_x_i);
    cudaGetSymbolAddress((void**)&xnr,  g_xn_r);
    cudaGetSymbolAddress((void**)&xni,  g_xn_i);
    cudaGetSymbolAddress((void**)&dr,   g_d_r);
    cudaGetSymbolAddress((void**)&di,   g_d_i);
    cudaGetSymbolAddress((void**)&xnb,  g_xnb);
    cudaGetSymbolAddress((void**)&wb,   g_wb);
    cudaGetSymbolAddress((void**)&wTb,  g_wTb);
    cudaGetSymbolAddress((void**)&atb,  g_atb);
    cudaGetSymbolAddress((void**)&attnb,g_attnb);
    cudaGetSymbolAddress((void**)&qkvb, g_qkvb);
    cudaGetSymbolAddress((void**)&outb, g_outb);
    cudaGetSymbolAddress((void**)&ffb,  g_ffb);

    cudaFuncSetAttribute(mma_gemm<0,false>, cudaFuncAttributeMaxDynamicSharedMemorySize, DSMEM_BYTES);
    cudaFuncSetAttribute(mma_gemm<1,true >, cudaFuncAttributeMaxDynamicSharedMemorySize, DSMEM_BYTES);
    cudaFuncSetAttribute(mma_gemm<2,false>, cudaFuncAttributeMaxDynamicSharedMemorySize, DSMEM_BYTES);
    cudaFuncSetAttribute(mma_gemm<3,false>, cudaFuncAttributeMaxDynamicSharedMemorySize, DSMEM_BYTES);
    cudaFuncSetAttribute(mma_gemm<4,false>, cudaFuncAttributeMaxDynamicSharedMemorySize, DSMEM_BYTES);

    copy_in_kernel<<<(PLN+255)/256, 256>>>(x_real, x_imag, xr, xi, PLN);
    conv_split_kernel<<<(WPL+255)/256, 256>>>(qkv_w_r, qkv_w_i, qkvb, WPL);
    conv_split_kernel<<<(WPL+255)/256, 256>>>(out_w_r, out_w_i, outb, WPL);
    conv_split_kernel<<<(WPL+255)/256, 256>>>(ff_w_r,  ff_w_i,  ffb,  WPL);

    const size_t sRow = (size_t)NN*DIM;   // 262144
    const size_t sNN  = (size_t)NN*NN;    // 262144

    for (int l = 0; l < DEPTH; l++){
        const size_t wo = (size_t)l*DIM*DIM;
        const size_t po = (size_t)l*DIM;

        // LN1 -> xn planes
        cln_kernel<<<ROWS,128>>>(xr,xi, ln1_g_r+po, ln1_b_r+po, ln1_g_i+po, ln1_b_i+po, xnr,xni, xnb);
        // QKV: w = xn @ Wqkv^T  -> w planes + wT planes
        mma_gemm<0,false><<<dim3(8,16,1),256,DSMEM_BYTES>>>(
            xnb, PLN, DIM, 0,0,  qkvb+wo, WPL, DIM, 0,0,  DIM, 1.0f,
            nullptr,nullptr, DIM, 0,0,  wb, PLN,  wTb, PLN,
            nullptr,nullptr, nullptr,nullptr, nullptr,nullptr, 0);
        // dots = scale * w @ conj(w)^T  (K=64, 32 batch-heads)
        mma_gemm<1,true><<<dim3(8,4,32),256,DSMEM_BYTES>>>(
            wb, PLN, DIM, sRow, DH,  wb, PLN, DIM, sRow, DH,  DH, ATT_SCALE,
            dr, di, NN, 8*sNN, sNN,  nullptr,0, nullptr,0,
            nullptr,nullptr, nullptr,nullptr, nullptr,nullptr, 0);
        // magnitude softmax -> attn planes
        csoftmax_kernel<<<BB*HEADS*NN/8,256>>>(dr, di, attnb);
        // at = attn @ wT^T  (K=512)
        mma_gemm<2,false><<<dim3(1,4,32),256,DSMEM_BYTES>>>(
            attnb, PLA, NN, 8*sNN, sNN,  wTb, PLN, NN, sRow, (size_t)DH*NN,  NN, 1.0f,
            nullptr,nullptr, DIM, sRow, DH,  atb, PLN,  nullptr,0,
            nullptr,nullptr, nullptr,nullptr, nullptr,nullptr, 0);
        // x = at @ Wout^T + bias + x
        mma_gemm<3,false><<<dim3(8,16,1),256,DSMEM_BYTES>>>(
            atb, PLN, DIM, 0,0,  outb+wo, WPL, DIM, 0,0,  DIM, 1.0f,
            xr, xi, DIM, 0,0,  nullptr,0, nullptr,0,
            out_b_r+po, out_b_i+po, nullptr,nullptr, nullptr,nullptr, 0);
        // LN2 -> xn fp32 + planes
        cln_kernel<<<ROWS,128>>>(xr,xi, ln2_g_r+po, ln2_b_r+po, ln2_g_i+po, ln2_b_i+po, xnr,xni, xnb);
        // x = crelu(xn + ss*(xn @ Wff^T) - ss*lm)
        mma_gemm<4,false><<<dim3(8,16,1),256,DSMEM_BYTES>>>(
            xnb, PLN, DIM, 0,0,  ffb+wo, WPL, DIM, 0,0,  DIM, 1.0f,
            xr, xi, DIM, 0,0,  nullptr,0, nullptr,0,
            nullptr,nullptr, xnr, xni, step_sz, lambd, l);
    }

    copy_out_kernel<<<(PLN+255)/256, 256>>>(xr, xi, (float*)d_out, PLN);
}

// round 9
// speedup vs baseline: 1.6734x; 1.0708x over previous
#include <cuda_runtime.h>
#include <cuda_bf16.h>
#include <math.h>
#include <stdint.h>

#define BB 4
#define NN 512
#define DIM 512
#define HEADS 8
#define DH 64
#define DEPTH 4
#define ROWS (BB*NN)
#define ATT_SCALE 0.125f
#define LN_EPS 1e-5f
#define PLN (ROWS*DIM)          // 1048576
#define PLA (32*NN*NN)          // 8388608
#define WPL (DEPTH*DIM*DIM)     // 1048576

// ---------------- scratch ----------------------------------------------------
__device__ float g_x_r [PLN];
__device__ float g_x_i [PLN];
__device__ float g_xn_r[PLN];
__device__ float g_xn_i[PLN];
__device__ float g_d_r [PLA];
__device__ float g_d_i [PLA];
// bf16 planes: 0=re_hi 1=re_lo 2=im_hi 3=im_lo
__device__ alignas(16) __nv_bfloat16 g_xnb [4*PLN];
__device__ alignas(16) __nv_bfloat16 g_wb  [4*PLN];
__device__ alignas(16) __nv_bfloat16 g_atb [4*PLN];
__device__ alignas(16) __nv_bfloat16 g_attnb[(size_t)4*PLA];
__device__ alignas(16) __nv_bfloat16 g_qkvb[4*WPL];
__device__ alignas(16) __nv_bfloat16 g_outb[4*WPL];
__device__ alignas(16) __nv_bfloat16 g_ffb [4*WPL];

// ---------------- helpers -----------------------------------------------------
__device__ __forceinline__ float warp_sum(float v){
    #pragma unroll
    for (int o=16;o;o>>=1) v += __shfl_xor_sync(0xffffffffu, v, o);
    return v;
}
__device__ __forceinline__ float warp_max(float v){
    #pragma unroll
    for (int o=16;o;o>>=1) v = fmaxf(v, __shfl_xor_sync(0xffffffffu, v, o));
    return v;
}
__device__ __forceinline__ void cpa16(unsigned dst, const void* src){
    asm volatile("cp.async.cg.shared.global [%0], [%1], 16;" :: "r"(dst), "l"(src));
}
#define CP_COMMIT() asm volatile("cp.async.commit_group;")
#define CP_WAIT1()  asm volatile("cp.async.wait_group 1;")
#define CP_WAIT0()  asm volatile("cp.async.wait_group 0;")

__device__ __forceinline__ void ldsm4(unsigned &r0,unsigned &r1,unsigned &r2,unsigned &r3,unsigned a){
    asm volatile("ldmatrix.sync.aligned.m8n8.x4.shared.b16 {%0,%1,%2,%3}, [%4];"
        : "=r"(r0),"=r"(r1),"=r"(r2),"=r"(r3) : "r"(a));
}
__device__ __forceinline__ void ldsm4t(unsigned &r0,unsigned &r1,unsigned &r2,unsigned &r3,unsigned a){
    asm volatile("ldmatrix.sync.aligned.m8n8.x4.trans.shared.b16 {%0,%1,%2,%3}, [%4];"
        : "=r"(r0),"=r"(r1),"=r"(r2),"=r"(r3) : "r"(a));
}
__device__ __forceinline__ void mmabf(float* d, const unsigned* a, const unsigned* b){
    asm volatile("mma.sync.aligned.m16n8k16.row.col.f32.bf16.bf16.f32 "
        "{%0,%1,%2,%3}, {%4,%5,%6,%7}, {%8,%9}, {%0,%1,%2,%3};"
        : "+f"(d[0]),"+f"(d[1]),"+f"(d[2]),"+f"(d[3])
        : "r"(a[0]),"r"(a[1]),"r"(a[2]),"r"(a[3]), "r"(b[0]),"r"(b[1]));
}

__device__ __forceinline__ void store_split4(__nv_bfloat16* p, size_t pl, size_t o, float4 v){
    __nv_bfloat16 h0=__float2bfloat16_rn(v.x), h1=__float2bfloat16_rn(v.y);
    __nv_bfloat16 h2=__float2bfloat16_rn(v.z), h3=__float2bfloat16_rn(v.w);
    *(__nv_bfloat162*)(p+o)   = __halves2bfloat162(h0,h1);
    *(__nv_bfloat162*)(p+o+2) = __halves2bfloat162(h2,h3);
    *(__nv_bfloat162*)(p+pl+o)   = __halves2bfloat162(
        __float2bfloat16_rn(v.x-__bfloat162float(h0)), __float2bfloat16_rn(v.y-__bfloat162float(h1)));
    *(__nv_bfloat162*)(p+pl+o+2) = __halves2bfloat162(
        __float2bfloat16_rn(v.z-__bfloat162float(h2)), __float2bfloat16_rn(v.w-__bfloat162float(h3)));
}

// ---------------- small kernels -----------------------------------------------
__global__ void copy_in_kernel(const float* __restrict__ a, const float* __restrict__ b,
                               float* __restrict__ xr, float* __restrict__ xi, int n){
    int i = blockIdx.x*blockDim.x + threadIdx.x;
    if (i < n){ xr[i] = a[i]; xi[i] = b[i]; }
}
__global__ void copy_out_kernel(const float* __restrict__ xr, const float* __restrict__ xi,
                                float* __restrict__ out, int n){
    int i = blockIdx.x*blockDim.x + threadIdx.x;
    if (i < n){ out[i] = xr[i]; out[n+i] = xi[i]; }
}
__global__ void conv_split_kernel(const float* __restrict__ r, const float* __restrict__ im,
                                  __nv_bfloat16* __restrict__ dst, int n){
    int x = blockIdx.x*blockDim.x + threadIdx.x;
    if (x >= n) return;
    float v = r[x];
    __nv_bfloat16 h = __float2bfloat16_rn(v);
    dst[x] = h; dst[n + x] = __float2bfloat16_rn(v - __bfloat162float(h));
    v = im[x];
    h = __float2bfloat16_rn(v);
    dst[2*(size_t)n + x] = h; dst[3*(size_t)n + x] = __float2bfloat16_rn(v - __bfloat162float(h));
}

__global__ __launch_bounds__(128)
void cln_kernel(const float* __restrict__ xr, const float* __restrict__ xi,
                const float* __restrict__ gr, const float* __restrict__ br,
                const float* __restrict__ gi, const float* __restrict__ bi,
                float* __restrict__ outr, float* __restrict__ outi,
                __nv_bfloat16* __restrict__ outb)
{
    const int row = blockIdx.x;
    const int t   = threadIdx.x;
    const float4 vr = reinterpret_cast<const float4*>(xr + (size_t)row*DIM)[t];
    const float4 vi = reinterpret_cast<const float4*>(xi + (size_t)row*DIM)[t];

    float sr  = vr.x+vr.y+vr.z+vr.w;
    float s2r = vr.x*vr.x+vr.y*vr.y+vr.z*vr.z+vr.w*vr.w;
    float si  = vi.x+vi.y+vi.z+vi.w;
    float s2i = vi.x*vi.x+vi.y*vi.y+vi.z*vi.z+vi.w*vi.w;

    sr = warp_sum(sr); s2r = warp_sum(s2r); si = warp_sum(si); s2i = warp_sum(s2i);

    __shared__ float red[4][4];
    const int wid = t >> 5, lane = t & 31;
    if (lane == 0){ red[wid][0]=sr; red[wid][1]=s2r; red[wid][2]=si; red[wid][3]=s2i; }
    __syncthreads();
    float tr=0,t2r=0,ti=0,t2i=0;
    #pragma unroll
    for (int w=0; w<4; w++){ tr+=red[w][0]; t2r+=red[w][1]; ti+=red[w][2]; t2i+=red[w][3]; }

    const float inv = 1.0f/DIM;
    const float mr = tr*inv,  vvr = t2r*inv - mr*mr;
    const float mi = ti*inv,  vvi = t2i*inv - mi*mi;
    const float rr = rsqrtf(vvr + LN_EPS);
    const float ri = rsqrtf(vvi + LN_EPS);

    const float4 g4r = reinterpret_cast<const float4*>(gr)[t];
    const float4 b4r = reinterpret_cast<const float4*>(br)[t];
    const float4 g4i = reinterpret_cast<const float4*>(gi)[t];
    const float4 b4i = reinterpret_cast<const float4*>(bi)[t];

    float4 orr, oii;
    orr.x = (vr.x-mr)*rr*g4r.x + b4r.x;  oii.x = (vi.x-mi)*ri*g4i.x + b4i.x;
    orr.y = (vr.y-mr)*rr*g4r.y + b4r.y;  oii.y = (vi.y-mi)*ri*g4i.y + b4i.y;
    orr.z = (vr.z-mr)*rr*g4r.z + b4r.z;  oii.z = (vi.z-mi)*ri*g4i.z + b4i.z;
    orr.w = (vr.w-mr)*rr*g4r.w + b4r.w;  oii.w = (vi.w-mi)*ri*g4i.w + b4i.w;
    reinterpret_cast<float4*>(outr + (size_t)row*DIM)[t] = orr;
    reinterpret_cast<float4*>(outi + (size_t)row*DIM)[t] = oii;

    const size_t o = (size_t)row*DIM + 4*t;
    store_split4(outb,                 PLN, o, orr);
    store_split4(outb + (size_t)2*PLN, PLN, o, oii);
}

__global__ __launch_bounds__(256)
void csoftmax_kernel(const float* __restrict__ zr, const float* __restrict__ zi,
                     __nv_bfloat16* __restrict__ attn)
{
    const int wid = threadIdx.x >> 5, lane = threadIdx.x & 31;
    const size_t row = (size_t)blockIdx.x*8 + wid;
    const float* pr = zr + row*NN;
    const float* pi = zi + row*NN;

    float4 vr[4], vi[4];
    #pragma unroll
    for (int u=0;u<4;u++){
        vr[u] = reinterpret_cast<const float4*>(pr)[lane + 32*u];
        vi[u] = reinterpret_cast<const float4*>(pi)[lane + 32*u];
    }
    float m[16];
    #pragma unroll
    for (int u=0;u<4;u++){
        m[4*u+0] = sqrtf(vr[u].x*vr[u].x + vi[u].x*vi[u].x);
        m[4*u+1] = sqrtf(vr[u].y*vr[u].y + vi[u].y*vi[u].y);
        m[4*u+2] = sqrtf(vr[u].z*vr[u].z + vi[u].z*vi[u].z);
        m[4*u+3] = sqrtf(vr[u].w*vr[u].w + vi[u].w*vi[u].w);
    }
    float mx = m[0];
    #pragma unroll
    for (int e=1;e<16;e++) mx = fmaxf(mx, m[e]);
    mx = warp_max(mx);

    float ex[16]; float s = 0.f;
    #pragma unroll
    for (int e=0;e<16;e++){ ex[e] = __expf(m[e] - mx); s += ex[e]; }
    s = warp_sum(s);
    const float inv = 1.0f / s;

    #pragma unroll
    for (int u=0;u<4;u++){
        float4 ar, ai;
        #pragma unroll
        for (int q=0;q<4;q++){
            const float mm = m[4*u+q];
            const float p  = ex[4*u+q]*inv;
            float wr = (q==0? vr[u].x : q==1? vr[u].y : q==2? vr[u].z : vr[u].w);
            float wi = (q==0? vi[u].x : q==1? vi[u].y : q==2? vi[u].z : vi[u].w);
            float orv, oiv;
            if (mm > 0.f){ const float sc = p/mm; orv = wr*sc; oiv = wi*sc; }
            else         { orv = p; oiv = 0.f; }
            if (q==0){ ar.x=orv; ai.x=oiv; } else if (q==1){ ar.y=orv; ai.y=oiv; }
            else if (q==2){ ar.z=orv; ai.z=oiv; } else { ar.w=orv; ai.w=oiv; }
        }
        const size_t o = row*NN + 4*(lane + 32*u);
        store_split4(attn,                 PLA, o, ar);
        store_split4(attn + (size_t)2*PLA, PLA, o, ai);
    }
}

// ================= mma.sync bf16 complex GEMM ==================================
#define RS 48
#define RSB 144                          // trans-B row stride (64 cols * 2B + 16 pad)
#define APLANE (128*RS)                  // 6144 B
#define BPLANE (64*RS)                   // 3072 B (trans uses 16*144=2304 <= 3072)
#define STAGE_B (4*APLANE + 4*BPLANE)    // 36864 B
#define NSTG 3
#define DSMEM_BYTES (NSTG*STAGE_B + 128)

template<bool BTRANS>
__device__ __forceinline__ void load_stage(unsigned sb,
    const __nv_bfloat16* A, size_t ap, int lda,
    const __nv_bfloat16* B, size_t bp, int ldb, int k0, int tid)
{
    const int row = tid >> 1, half = tid & 1;
    #pragma unroll
    for (int p=0;p<4;p++)
        cpa16(sb + p*APLANE + row*RS + half*16, A + p*ap + (size_t)row*lda + k0 + half*8);
    if (BTRANS){
        #pragma unroll
        for (int c=0;c<2;c++){
            const int idx = tid*2 + c;        // 0..511
            const int p  = idx >> 7;
            const int rr = (idx >> 3) & 15;   // k row
            const int cc = idx & 7;           // 16B chunk over 64 n-cols
            cpa16(sb + 4*APLANE + p*BPLANE + rr*RSB + cc*16,
                  B + (size_t)p*bp + (size_t)(k0+rr)*ldb + cc*8);
        }
    } else if (tid < 128){
        #pragma unroll
        for (int p=0;p<4;p++)
            cpa16(sb + 4*APLANE + p*BPLANE + row*RS + half*16, B + p*bp + (size_t)row*ldb + k0 + half*8);
    }
    CP_COMMIT();
}

template<bool CONJ, bool BTRANS>
__device__ __forceinline__ void compute_stage(unsigned sb, int wm, int wn, int lane,
    float cre[2][4][4], float cim[2][4][4])
{
    const unsigned aoff = (unsigned)((lane & 15)*RS + (lane >> 4)*16);
    const int bg = lane >> 3;
    const unsigned boff  = (unsigned)((((bg & 2) << 2) + (lane & 7))*RS + (bg & 1)*16);
    const int krow = (lane & 7) + ((lane >> 3) & 1)*8;
    const int nc8  = lane >> 4;

    unsigned Arh[2][4], Arl[2][4], Aih[2][4], Ail[2][4];
    #pragma unroll
    for (int mf=0; mf<2; mf++){
        const unsigned ab = sb + (unsigned)(wm + mf*16)*RS + aoff;
        ldsm4(Arh[mf][0],Arh[mf][1],Arh[mf][2],Arh[mf][3], ab);
        ldsm4(Arl[mf][0],Arl[mf][1],Arl[mf][2],Arl[mf][3], ab + APLANE);
        ldsm4(Aih[mf][0],Aih[mf][1],Aih[mf][2],Aih[mf][3], ab + 2*APLANE);
        ldsm4(Ail[mf][0],Ail[mf][1],Ail[mf][2],Ail[mf][3], ab + 3*APLANE);
    }
    unsigned Bh[4][2], Bl[4][2];

    #define LOAD_B(PLANE_OFF)                                                       \
    do{                                                                             \
        _Pragma("unroll")                                                           \
        for (int np=0; np<2; np++){                                                 \
            unsigned r0,r1,r2,r3;                                                   \
            if (!BTRANS){                                                           \
                const unsigned bb = sb + 4*APLANE + (PLANE_OFF) +                   \
                                    (unsigned)(wn + np*16)*RS + boff;               \
                ldsm4(r0,r1,r2,r3, bb);                                             \
                Bh[2*np][0]=r0; Bh[2*np][1]=r1; Bh[2*np+1][0]=r2; Bh[2*np+1][1]=r3; \
                ldsm4(r0,r1,r2,r3, bb + BPLANE);                                    \
                Bl[2*np][0]=r0; Bl[2*np][1]=r1; Bl[2*np+1][0]=r2; Bl[2*np+1][1]=r3; \
            } else {                                                                \
                const unsigned bb = sb + 4*APLANE + (PLANE_OFF) + krow*RSB +        \
                                    (unsigned)(wn + np*16 + nc8*8)*2;               \
                ldsm4t(r0,r1,r2,r3, bb);                                            \
                Bh[2*np][0]=r0; Bh[2*np][1]=r1; Bh[2*np+1][0]=r2; Bh[2*np+1][1]=r3; \
                ldsm4t(r0,r1,r2,r3, bb + BPLANE);                                   \
                Bl[2*np][0]=r0; Bl[2*np][1]=r1; Bl[2*np+1][0]=r2; Bl[2*np+1][1]=r3; \
            }                                                                       \
        }                                                                           \
    }while(0)

    // ---- half 1: B = real planes
    LOAD_B(0u);
    #pragma unroll
    for (int mf=0; mf<2; mf++)
    #pragma unroll
    for (int nf=0; nf<4; nf++){
        mmabf(cre[mf][nf], Arh[mf], Bh[nf]);
        mmabf(cre[mf][nf], Arh[mf], Bl[nf]);
        mmabf(cre[mf][nf], Arl[mf], Bh[nf]);
        mmabf(cim[mf][nf], Aih[mf], Bh[nf]);
        mmabf(cim[mf][nf], Aih[mf], Bl[nf]);
        mmabf(cim[mf][nf], Ail[mf], Bh[nf]);
    }
    // ---- half 2: B = imag planes
    LOAD_B(2u*BPLANE);
    if (CONJ){
        #pragma unroll
        for (int mf=0; mf<2; mf++)
        #pragma unroll
        for (int nf=0; nf<4; nf++){
            mmabf(cre[mf][nf], Aih[mf], Bh[nf]);
            mmabf(cre[mf][nf], Aih[mf], Bl[nf]);
            mmabf(cre[mf][nf], Ail[mf], Bh[nf]);
        }
        #pragma unroll
        for (int nf=0; nf<4; nf++){
            Bh[nf][0]^=0x80008000u; Bh[nf][1]^=0x80008000u;
            Bl[nf][0]^=0x80008000u; Bl[nf][1]^=0x80008000u;
        }
        #pragma unroll
        for (int mf=0; mf<2; mf++)
        #pragma unroll
        for (int nf=0; nf<4; nf++){
            mmabf(cim[mf][nf], Arh[mf], Bh[nf]);
            mmabf(cim[mf][nf], Arh[mf], Bl[nf]);
            mmabf(cim[mf][nf], Arl[mf], Bh[nf]);
        }
    } else {
        #pragma unroll
        for (int mf=0; mf<2; mf++)
        #pragma unroll
        for (int nf=0; nf<4; nf++){
            mmabf(cim[mf][nf], Arh[mf], Bh[nf]);
            mmabf(cim[mf][nf], Arh[mf], Bl[nf]);
            mmabf(cim[mf][nf], Arl[mf], Bh[nf]);
        }
        #pragma unroll
        for (int nf=0; nf<4; nf++){
            Bh[nf][0]^=0x80008000u; Bh[nf][1]^=0x80008000u;
            Bl[nf][0]^=0x80008000u; Bl[nf][1]^=0x80008000u;
        }
        #pragma unroll
        for (int mf=0; mf<2; mf++)
        #pragma unroll
        for (int nf=0; nf<4; nf++){
            mmabf(cre[mf][nf], Aih[mf], Bh[nf]);
            mmabf(cre[mf][nf], Aih[mf], Bl[nf]);
            mmabf(cre[mf][nf], Ail[mf], Bh[nf]);
        }
    }
    #undef LOAD_B
}

// EPI: 0=W planes, 1=DOTS (fp32*alpha), 2=AT planes, 3=OUT (x+=acc+bias), 4=FF (crelu)
template<int EPI, bool CONJ, bool BTRANS>
__global__ __launch_bounds__(256, 1)
void mma_gemm(const __nv_bfloat16* __restrict__ Ab, size_t ap, int lda, size_t aB, size_t aBH,
              const __nv_bfloat16* __restrict__ Bb, size_t bp, int ldb, size_t bB, size_t bBH,
              int K, float alpha,
              float* Cr, float* Ci, int ldc, size_t cB, size_t cBH,
              __nv_bfloat16* Ob, size_t op,
              const float* __restrict__ biasR, const float* __restrict__ biasI,
              const float* __restrict__ Xr, const float* __restrict__ Xi,
              const float* __restrict__ ssp, const float* __restrict__ lmp, int layer)
{
    extern __shared__ char dsmc[];
    const unsigned base = ((unsigned)__cvta_generic_to_shared(dsmc) + 127u) & ~127u;

    const int tid = threadIdx.x;
    const int lane = tid & 31, wid = tid >> 5;
    const int wm = (wid & 3)*32, wn = (wid >> 2)*32;
    const int zb = blockIdx.z >> 3, zh = blockIdx.z & 7;
    const int m0 = blockIdx.y * 128, n0 = blockIdx.x * 64;

    const __nv_bfloat16* At = Ab + (size_t)zb*aB + (size_t)zh*aBH + (size_t)m0*lda;
    const __nv_bfloat16* Bt = Bb + (size_t)zb*bB + (size_t)zh*bBH
                            + (BTRANS ? (size_t)n0 : (size_t)n0*ldb);
    const size_t Coff = (size_t)zb*cB + (size_t)zh*cBH;

    float cre[2][4][4] = {}, cim[2][4][4] = {};

    const int NIT = K >> 4;
    load_stage<BTRANS>(base, At, ap, lda, Bt, bp, ldb, 0, tid);
    if (NIT > 1) load_stage<BTRANS>(base + STAGE_B, At, ap, lda, Bt, bp, ldb, 16, tid);
    else CP_COMMIT();

    int sidx = 0;
    for (int it = 0; it < NIT; it++){
        if (it + 1 < NIT) CP_WAIT1(); else CP_WAIT0();
        __syncthreads();
        if (it + 2 < NIT){
            int sn = sidx + 2; if (sn >= NSTG) sn -= NSTG;
            load_stage<BTRANS>(base + (unsigned)sn*STAGE_B, At, ap, lda, Bt, bp, ldb, (it+2) << 4, tid);
        } else {
            CP_COMMIT();
        }
        compute_stage<CONJ,BTRANS>(base + (unsigned)sidx*STAGE_B, wm, wn, lane, cre, cim);
        sidx++; if (sidx == NSTG) sidx = 0;
    }

    float ss = 0.f, lm = 0.f;
    if (EPI == 4){ ss = log1pf(expf(ssp[layer])); lm = log1pf(expf(lmp[layer])); }

    #pragma unroll
    for (int mf=0; mf<2; mf++)
    #pragma unroll
    for (int nf=0; nf<4; nf++){
        const int row0 = m0 + wm + mf*16 + (lane >> 2);
        const int col  = n0 + wn + nf*8 + (lane & 3)*2;
        #pragma unroll
        for (int h=0; h<2; h++){
            const int r = row0 + h*8;
            float vr0 = cre[mf][nf][2*h]   * alpha;
            float vr1 = cre[mf][nf][2*h+1] * alpha;
            float vi0 = cim[mf][nf][2*h]   * alpha;
            float vi1 = cim[mf][nf][2*h+1] * alpha;
            const size_t a = Coff + (size_t)r*ldc + col;
            if (EPI == 1){
                Cr[a] = vr0; Cr[a+1] = vr1; Ci[a] = vi0; Ci[a+1] = vi1;
            } else if (EPI == 3){
                Cr[a]   = vr0 + biasR[col]   + Cr[a];
                Cr[a+1] = vr1 + biasR[col+1] + Cr[a+1];
                Ci[a]   = vi0 + biasI[col]   + Ci[a];
                Ci[a+1] = vi1 + biasI[col+1] + Ci[a+1];
            } else if (EPI == 4){
                Cr[a]   = fmaxf(fmaf(ss, vr0, Xr[a])   - ss*lm, 0.f);
                Cr[a+1] = fmaxf(fmaf(ss, vr1, Xr[a+1]) - ss*lm, 0.f);
                Ci[a]   = fmaxf(fmaf(ss, vi0, Xi[a]),   0.f);
                Ci[a+1] = fmaxf(fmaf(ss, vi1, Xi[a+1]), 0.f);
            } else {
                __nv_bfloat16 h0 = __float2bfloat16_rn(vr0), h1 = __float2bfloat16_rn(vr1);
                *(__nv_bfloat162*)(Ob + a) = __halves2bfloat162(h0, h1);
                *(__nv_bfloat162*)(Ob + op + a) = __halves2bfloat162(
                    __float2bfloat16_rn(vr0 - __bfloat162float(h0)),
                    __float2bfloat16_rn(vr1 - __bfloat162float(h1)));
                __nv_bfloat16 g0 = __float2bfloat16_rn(vi0), g1 = __float2bfloat16_rn(vi1);
                *(__nv_bfloat162*)(Ob + 2*op + a) = __halves2bfloat162(g0, g1);
                *(__nv_bfloat162*)(Ob + 3*op + a) = __halves2bfloat162(
                    __float2bfloat16_rn(vi0 - __bfloat162float(g0)),
                    __float2bfloat16_rn(vi1 - __bfloat162float(g1)));
            }
        }
    }
}

// ---------------- launch --------------------------------------------------------
extern "C" void kernel_launch(void* const* d_in, const int* in_sizes, int n_in,
                              void* d_out, int out_size)
{
    const float* x_real   = (const float*)d_in[0];
    const float* x_imag   = (const float*)d_in[1];
    const float* ln1_g_r  = (const float*)d_in[2];
    const float* ln1_b_r  = (const float*)d_in[3];
    const float* ln1_g_i  = (const float*)d_in[4];
    const float* ln1_b_i  = (const float*)d_in[5];
    const float* ln2_g_r  = (const float*)d_in[6];
    const float* ln2_b_r  = (const float*)d_in[7];
    const float* ln2_g_i  = (const float*)d_in[8];
    const float* ln2_b_i  = (const float*)d_in[9];
    const float* qkv_w_r  = (const float*)d_in[10];
    const float* qkv_w_i  = (const float*)d_in[11];
    const float* out_w_r  = (const float*)d_in[12];
    const float* out_w_i  = (const float*)d_in[13];
    const float* out_b_r  = (const float*)d_in[14];
    const float* out_b_i  = (const float*)d_in[15];
    const float* ff_w_r   = (const float*)d_in[16];
    const float* ff_w_i   = (const float*)d_in[17];
    const float* step_sz  = (const float*)d_in[18];
    const float* lambd    = (const float*)d_in[19];

    float *xr,*xi,*xnr,*xni,*dr,*di;
    __nv_bfloat16 *xnb,*wb,*atb,*attnb,*qkvb,*outb,*ffb;
    cudaGetSymbolAddress((void**)&xr,   g_x_r);
    cudaGetSymbolAddress((void**)&xi,   g_x_i);
    cudaGetSymbolAddress((void**)&xnr,  g_xn_r);
    cudaGetSymbolAddress((void**)&xni,  g_xn_i);
    cudaGetSymbolAddress((void**)&dr,   g_d_r);
    cudaGetSymbolAddress((void**)&di,   g_d_i);
    cudaGetSymbolAddress((void**)&xnb,  g_xnb);
    cudaGetSymbolAddress((void**)&wb,   g_wb);
    cudaGetSymbolAddress((void**)&atb,  g_atb);
    cudaGetSymbolAddress((void**)&attnb,g_attnb);
    cudaGetSymbolAddress((void**)&qkvb, g_qkvb);
    cudaGetSymbolAddress((void**)&outb, g_outb);
    cudaGetSymbolAddress((void**)&ffb,  g_ffb);

    cudaFuncSetAttribute(mma_gemm<0,false,false>, cudaFuncAttributeMaxDynamicSharedMemorySize, DSMEM_BYTES);
    cudaFuncSetAttribute(mma_gemm<1,true ,false>, cudaFuncAttributeMaxDynamicSharedMemorySize, DSMEM_BYTES);
    cudaFuncSetAttribute(mma_gemm<2,false,true >, cudaFuncAttributeMaxDynamicSharedMemorySize, DSMEM_BYTES);
    cudaFuncSetAttribute(mma_gemm<3,false,false>, cudaFuncAttributeMaxDynamicSharedMemorySize, DSMEM_BYTES);
    cudaFuncSetAttribute(mma_gemm<4,false,false>, cudaFuncAttributeMaxDynamicSharedMemorySize, DSMEM_BYTES);

    copy_in_kernel<<<(PLN+255)/256, 256>>>(x_real, x_imag, xr, xi, PLN);
    conv_split_kernel<<<(WPL+255)/256, 256>>>(qkv_w_r, qkv_w_i, qkvb, WPL);
    conv_split_kernel<<<(WPL+255)/256, 256>>>(out_w_r, out_w_i, outb, WPL);
    conv_split_kernel<<<(WPL+255)/256, 256>>>(ff_w_r,  ff_w_i,  ffb,  WPL);

    const size_t sRow = (size_t)NN*DIM;   // 262144
    const size_t sNN  = (size_t)NN*NN;    // 262144

    for (int l = 0; l < DEPTH; l++){
        const size_t wo = (size_t)l*DIM*DIM;
        const size_t po = (size_t)l*DIM;

        // LN1 -> xn planes
        cln_kernel<<<ROWS,128>>>(xr,xi, ln1_g_r+po, ln1_b_r+po, ln1_g_i+po, ln1_b_i+po, xnr,xni, xnb);
        // QKV: w = xn @ Wqkv^T -> w planes
        mma_gemm<0,false,false><<<dim3(8,16,1),256,DSMEM_BYTES>>>(
            xnb, PLN, DIM, 0,0,  qkvb+wo, WPL, DIM, 0,0,  DIM, 1.0f,
            nullptr,nullptr, DIM, 0,0,  wb, PLN,
            nullptr,nullptr, nullptr,nullptr, nullptr,nullptr, 0);
        // dots = scale * w @ conj(w)^T (K=64, 32 batch-heads)
        mma_gemm<1,true,false><<<dim3(8,4,32),256,DSMEM_BYTES>>>(
            wb, PLN, DIM, sRow, DH,  wb, PLN, DIM, sRow, DH,  DH, ATT_SCALE,
            dr, di, NN, 8*sNN, sNN,  nullptr,0,
            nullptr,nullptr, nullptr,nullptr, nullptr,nullptr, 0);
        // magnitude softmax -> attn planes
        csoftmax_kernel<<<BB*HEADS*NN/8,256>>>(dr, di, attnb);
        // at = attn @ w (B read NN via trans ldmatrix; K=512)
        mma_gemm<2,false,true><<<dim3(1,4,32),256,DSMEM_BYTES>>>(
            attnb, PLA, NN, 8*sNN, sNN,  wb, PLN, DIM, sRow, DH,  NN, 1.0f,
            nullptr,nullptr, DIM, sRow, DH,  atb, PLN,
            nullptr,nullptr, nullptr,nullptr, nullptr,nullptr, 0);
        // x = at @ Wout^T + bias + x
        mma_gemm<3,false,false><<<dim3(8,16,1),256,DSMEM_BYTES>>>(
            atb, PLN, DIM, 0,0,  outb+wo, WPL, DIM, 0,0,  DIM, 1.0f,
            xr, xi, DIM, 0,0,  nullptr,0,
            out_b_r+po, out_b_i+po, nullptr,nullptr, nullptr,nullptr, 0);
        // LN2 -> xn fp32 + planes
        cln_kernel<<<ROWS,128>>>(xr,xi, ln2_g_r+po, ln2_b_r+po, ln2_g_i+po, ln2_b_i+po, xnr,xni, xnb);
        // x = crelu(xn + ss*(xn @ Wff^T) - ss*lm)
        mma_gemm<4,false,false><<<dim3(8,16,1),256,DSMEM_BYTES>>>(
            xnb, PLN, DIM, 0,0,  ffb+wo, WPL, DIM, 0,0,  DIM, 1.0f,
            xr, xi, DIM, 0,0,  nullptr,0,
            nullptr,nullptr, xnr, xni, step_sz, lambd, l);
    }

    copy_out_kernel<<<(PLN+255)/256, 256>>>(xr, xi, (float*)d_out, PLN);
}